// round 9
// baseline (speedup 1.0000x reference)
#include <cuda_runtime.h>
#include <climits>

// Problem constants
#define BB 64
#define PP 5000
#define GG 300
#define NC 20
#define SPLIT 10          // chunks per image in the main kernel
#define THREADS 256

// Scratch (device globals -- no allocation allowed)
__device__ int   g_winner[BB * GG];   // min pred index claiming each target
__device__ short g_bi[BB * PP];       // best target per pred, -1 if no candidate

// ---------------------------------------------------------------------------
// Kernel 1: reset winners + write tcls output tail
// out layout assumed: stats (B,P,3) fp32 followed by tcls (B,G) fp32
// ---------------------------------------------------------------------------
__global__ void mbe_init_kernel(const float* __restrict__ labels,
                                float* __restrict__ out_tcls) {
    int i = blockIdx.x * blockDim.x + threadIdx.x;
    if (i < BB * GG) {
        g_winner[i] = INT_MAX;
        out_tcls[i] = labels[i * 5 + 4];   // labels[(b*G+g)*5 + 4]
    }
}

// ---------------------------------------------------------------------------
// Kernel 2: per-pred best-target search with class-bucketed targets.
// grid.x = BB * SPLIT ; each block handles P/SPLIT preds of one image.
// ---------------------------------------------------------------------------
__global__ __launch_bounds__(THREADS)
void mbe_main_kernel(const float* __restrict__ preds,
                     const float* __restrict__ labels,
                     float* __restrict__ stats) {
    __shared__ float  s_lab[GG * 5];
    __shared__ float4 s_tbox[GG];      // scaled (x1,y1,x2,y2), sorted by class
    __shared__ float  s_tarea[GG];
    __shared__ int    s_start[NC + 1];
    __shared__ int    s_cnt[NC];

    const int b     = blockIdx.x / SPLIT;
    const int chunk = blockIdx.x % SPLIT;
    const int tid   = threadIdx.x;

    // Stage labels for this image
    const float* lab = labels + (long)b * GG * 5;
    for (int i = tid; i < GG * 5; i += THREADS) s_lab[i] = lab[i];
    if (tid < NC) s_cnt[tid] = 0;
    __syncthreads();

    // Class histogram
    for (int g = tid; g < GG; g += THREADS) {
        int c = (int)s_lab[g * 5 + 4];
        if ((unsigned)c < NC) atomicAdd(&s_cnt[c], 1);
    }
    __syncthreads();

    if (tid == 0) {
        int acc = 0;
        for (int c = 0; c < NC; c++) { s_start[c] = acc; acc += s_cnt[c]; }
        s_start[NC] = acc;
    }
    __syncthreads();

    // Stable counting-sort placement: one thread per class walks targets in
    // original order -> within-class original order preserved (argmax ties).
    if (tid < NC) {
        int pos = s_start[tid];
        for (int g = 0; g < GG; g++) {
            if ((int)s_lab[g * 5 + 4] == tid) {
                float x1 = s_lab[g * 5 + 0] * 512.0f;
                float y1 = s_lab[g * 5 + 1] * 512.0f;
                float x2 = s_lab[g * 5 + 2] * 512.0f;
                float y2 = s_lab[g * 5 + 3] * 512.0f;
                s_tbox[pos]  = make_float4(x1, y1, x2, y2);
                s_tarea[pos] = (x2 - x1) * (y2 - y1);
                pos++;
            }
        }
    }
    __syncthreads();

    const int winner_base = b * GG;
    const int pper = (PP + SPLIT - 1) / SPLIT;
    const int p0 = chunk * pper;
    const int p1 = (p0 + pper < PP) ? (p0 + pper) : PP;

    for (int p = p0 + tid; p < p1; p += THREADS) {
        const float* pr = preds + ((long)b * PP + p) * 6;
        float2 q0 = *(const float2*)(pr);       // x1, y1
        float2 q1 = *(const float2*)(pr + 2);   // x2, y2
        float2 q2 = *(const float2*)(pr + 4);   // score, cls

        float px1 = q0.x * 512.0f, py1 = q0.y * 512.0f;
        float px2 = q1.x * 512.0f, py2 = q1.y * 512.0f;
        float score = q2.x;
        float fcls  = q2.y;
        float parea = (px2 - px1) * (py2 - py1);
        int cls = (int)fcls;

        int   bi   = -1;
        float best = 0.5f;   // = IOU_THRESH: only > thresh targets can win

        if ((unsigned)cls < NC && score > 0.0f) {
            int t0 = s_start[cls], t1 = s_start[cls + 1];
            for (int t = t0; t < t1; t++) {
                float4 tb = s_tbox[t];
                float lx = fmaxf(px1, tb.x);
                float ly = fmaxf(py1, tb.y);
                float rx = fminf(px2, tb.z);
                float ry = fminf(py2, tb.w);
                float w = fmaxf(rx - lx, 0.0f);
                float h = fmaxf(ry - ly, 0.0f);
                float inter = w * h;
                if (inter > 0.0f) {
                    float denom = (parea + s_tarea[t]) - inter;  // ref op order
                    float iou = __fdiv_rn(inter, denom);          // IEEE div
                    if (iou > best) { best = iou; bi = t; }       // first-max
                }
            }
        }

        g_bi[b * PP + p] = (short)bi;
        if (bi >= 0) atomicMin(&g_winner[winner_base + bi], p);

        long o = ((long)b * PP + p) * 3;
        stats[o + 1] = score;
        stats[o + 2] = fcls;
    }
}

// ---------------------------------------------------------------------------
// Kernel 3: winner check -> correct flag
// ---------------------------------------------------------------------------
__global__ void mbe_fin_kernel(float* __restrict__ stats) {
    int i = blockIdx.x * blockDim.x + threadIdx.x;
    if (i < BB * PP) {
        int bi = g_bi[i];
        int b  = i / PP;
        int p  = i - b * PP;
        float c = 0.0f;
        if (bi >= 0 && g_winner[b * GG + bi] == p) c = 1.0f;
        stats[(long)i * 3] = c;
    }
}

// ---------------------------------------------------------------------------
extern "C" void kernel_launch(void* const* d_in, const int* in_sizes, int n_in,
                              void* d_out, int out_size) {
    const float* preds  = (const float*)d_in[0];   // (B,P,6)
    const float* labels = (const float*)d_in[1];   // (B,G,5)
    float* stats    = (float*)d_out;                       // (B,P,3)
    float* out_tcls = (float*)d_out + (long)BB * PP * 3;   // (B,G)

    (void)in_sizes; (void)n_in; (void)out_size;

    int initBlocks = (BB * GG + 255) / 256;
    mbe_init_kernel<<<initBlocks, 256>>>(labels, out_tcls);

    mbe_main_kernel<<<BB * SPLIT, THREADS>>>(preds, labels, stats);

    int finBlocks = (BB * PP + 255) / 256;
    mbe_fin_kernel<<<finBlocks, 256>>>(stats);
}

// round 10
// speedup vs baseline: 1.0007x; 1.0007x over previous
#include <cuda_runtime.h>
#include <climits>

// Problem constants
#define BB 64
#define PP 5000
#define GG 300
#define NC 20
#define SPLIT 10          // chunks per image in the main kernel
#define THREADS 256

// Scratch (device globals -- no allocation allowed)
__device__ int   g_winner[BB * GG];   // min pred index claiming each target
__device__ short g_bi[BB * PP];       // best target per pred, -1 if no candidate

// ---------------------------------------------------------------------------
// Kernel 1: reset winners + write tcls output tail
// out layout assumed: stats (B,P,3) fp32 followed by tcls (B,G) fp32
// ---------------------------------------------------------------------------
__global__ void mbe_init_kernel(const float* __restrict__ labels,
                                float* __restrict__ out_tcls) {
    int i = blockIdx.x * blockDim.x + threadIdx.x;
    if (i < BB * GG) {
        g_winner[i] = INT_MAX;
        out_tcls[i] = labels[i * 5 + 4];   // labels[(b*G+g)*5 + 4]
    }
}

// ---------------------------------------------------------------------------
// Kernel 2: per-pred best-target search with class-bucketed targets.
// grid.x = BB * SPLIT ; each block handles P/SPLIT preds of one image.
// ---------------------------------------------------------------------------
__global__ __launch_bounds__(THREADS)
void mbe_main_kernel(const float* __restrict__ preds,
                     const float* __restrict__ labels,
                     float* __restrict__ stats) {
    __shared__ float  s_lab[GG * 5];
    __shared__ float4 s_tbox[GG];      // scaled (x1,y1,x2,y2), sorted by class
    __shared__ float  s_tarea[GG];
    __shared__ int    s_start[NC + 1];
    __shared__ int    s_cnt[NC];

    const int b     = blockIdx.x / SPLIT;
    const int chunk = blockIdx.x % SPLIT;
    const int tid   = threadIdx.x;

    // Stage labels for this image
    const float* lab = labels + (long)b * GG * 5;
    for (int i = tid; i < GG * 5; i += THREADS) s_lab[i] = lab[i];
    if (tid < NC) s_cnt[tid] = 0;
    __syncthreads();

    // Class histogram
    for (int g = tid; g < GG; g += THREADS) {
        int c = (int)s_lab[g * 5 + 4];
        if ((unsigned)c < NC) atomicAdd(&s_cnt[c], 1);
    }
    __syncthreads();

    if (tid == 0) {
        int acc = 0;
        for (int c = 0; c < NC; c++) { s_start[c] = acc; acc += s_cnt[c]; }
        s_start[NC] = acc;
    }
    __syncthreads();

    // Stable counting-sort placement: one thread per class walks targets in
    // original order -> within-class original order preserved (argmax ties).
    if (tid < NC) {
        int pos = s_start[tid];
        for (int g = 0; g < GG; g++) {
            if ((int)s_lab[g * 5 + 4] == tid) {
                float x1 = s_lab[g * 5 + 0] * 512.0f;
                float y1 = s_lab[g * 5 + 1] * 512.0f;
                float x2 = s_lab[g * 5 + 2] * 512.0f;
                float y2 = s_lab[g * 5 + 3] * 512.0f;
                s_tbox[pos]  = make_float4(x1, y1, x2, y2);
                s_tarea[pos] = (x2 - x1) * (y2 - y1);
                pos++;
            }
        }
    }
    __syncthreads();

    const int winner_base = b * GG;
    const int pper = (PP + SPLIT - 1) / SPLIT;
    const int p0 = chunk * pper;
    const int p1 = (p0 + pper < PP) ? (p0 + pper) : PP;

    for (int p = p0 + tid; p < p1; p += THREADS) {
        const float* pr = preds + ((long)b * PP + p) * 6;
        float2 q0 = *(const float2*)(pr);       // x1, y1
        float2 q1 = *(const float2*)(pr + 2);   // x2, y2
        float2 q2 = *(const float2*)(pr + 4);   // score, cls

        float px1 = q0.x * 512.0f, py1 = q0.y * 512.0f;
        float px2 = q1.x * 512.0f, py2 = q1.y * 512.0f;
        float score = q2.x;
        float fcls  = q2.y;
        float parea = (px2 - px1) * (py2 - py1);
        int cls = (int)fcls;

        int   bi   = -1;
        float best = 0.5f;   // = IOU_THRESH: only > thresh targets can win

        if ((unsigned)cls < NC && score > 0.0f) {
            int t0 = s_start[cls], t1 = s_start[cls + 1];
            for (int t = t0; t < t1; t++) {
                float4 tb = s_tbox[t];
                float lx = fmaxf(px1, tb.x);
                float ly = fmaxf(py1, tb.y);
                float rx = fminf(px2, tb.z);
                float ry = fminf(py2, tb.w);
                float w = fmaxf(rx - lx, 0.0f);
                float h = fmaxf(ry - ly, 0.0f);
                float inter = w * h;
                if (inter > 0.0f) {
                    float denom = (parea + s_tarea[t]) - inter;  // ref op order
                    float iou = __fdiv_rn(inter, denom);          // IEEE div
                    if (iou > best) { best = iou; bi = t; }       // first-max
                }
            }
        }

        g_bi[b * PP + p] = (short)bi;
        if (bi >= 0) atomicMin(&g_winner[winner_base + bi], p);

        long o = ((long)b * PP + p) * 3;
        stats[o + 1] = score;
        stats[o + 2] = fcls;
    }
}

// ---------------------------------------------------------------------------
// Kernel 3: winner check -> correct flag
// ---------------------------------------------------------------------------
__global__ void mbe_fin_kernel(float* __restrict__ stats) {
    int i = blockIdx.x * blockDim.x + threadIdx.x;
    if (i < BB * PP) {
        int bi = g_bi[i];
        int b  = i / PP;
        int p  = i - b * PP;
        float c = 0.0f;
        if (bi >= 0 && g_winner[b * GG + bi] == p) c = 1.0f;
        stats[(long)i * 3] = c;
    }
}

// ---------------------------------------------------------------------------
extern "C" void kernel_launch(void* const* d_in, const int* in_sizes, int n_in,
                              void* d_out, int out_size) {
    const float* preds  = (const float*)d_in[0];   // (B,P,6)
    const float* labels = (const float*)d_in[1];   // (B,G,5)
    float* stats    = (float*)d_out;                       // (B,P,3)
    float* out_tcls = (float*)d_out + (long)BB * PP * 3;   // (B,G)

    (void)in_sizes; (void)n_in; (void)out_size;

    int initBlocks = (BB * GG + 255) / 256;
    mbe_init_kernel<<<initBlocks, 256>>>(labels, out_tcls);

    mbe_main_kernel<<<BB * SPLIT, THREADS>>>(preds, labels, stats);

    int finBlocks = (BB * PP + 255) / 256;
    mbe_fin_kernel<<<finBlocks, 256>>>(stats);
}

// round 11
// speedup vs baseline: 1.0056x; 1.0049x over previous
#include <cuda_runtime.h>
#include <climits>

// Problem constants
#define BB 64
#define PP 5000
#define GG 300
#define NC 20
#define SPLIT 10          // chunks per image in the main kernel
#define THREADS 256

// Scratch (device globals -- no allocation allowed)
__device__ int   g_winner[BB * GG];   // min pred index claiming each target
__device__ short g_bi[BB * PP];       // best target per pred, -1 if no candidate

// ---------------------------------------------------------------------------
// Kernel 1: reset winners + write tcls output tail
// out layout assumed: stats (B,P,3) fp32 followed by tcls (B,G) fp32
// ---------------------------------------------------------------------------
__global__ void mbe_init_kernel(const float* __restrict__ labels,
                                float* __restrict__ out_tcls) {
    int i = blockIdx.x * blockDim.x + threadIdx.x;
    if (i < BB * GG) {
        g_winner[i] = INT_MAX;
        out_tcls[i] = labels[i * 5 + 4];   // labels[(b*G+g)*5 + 4]
    }
}

// ---------------------------------------------------------------------------
// Kernel 2: per-pred best-target search with class-bucketed targets.
// grid.x = BB * SPLIT ; each block handles P/SPLIT preds of one image.
// ---------------------------------------------------------------------------
__global__ __launch_bounds__(THREADS)
void mbe_main_kernel(const float* __restrict__ preds,
                     const float* __restrict__ labels,
                     float* __restrict__ stats) {
    __shared__ float  s_lab[GG * 5];
    __shared__ float4 s_tbox[GG];      // scaled (x1,y1,x2,y2), sorted by class
    __shared__ float  s_tarea[GG];
    __shared__ int    s_start[NC + 1];
    __shared__ int    s_cnt[NC];

    const int b     = blockIdx.x / SPLIT;
    const int chunk = blockIdx.x % SPLIT;
    const int tid   = threadIdx.x;

    // Stage labels for this image
    const float* lab = labels + (long)b * GG * 5;
    for (int i = tid; i < GG * 5; i += THREADS) s_lab[i] = lab[i];
    if (tid < NC) s_cnt[tid] = 0;
    __syncthreads();

    // Class histogram
    for (int g = tid; g < GG; g += THREADS) {
        int c = (int)s_lab[g * 5 + 4];
        if ((unsigned)c < NC) atomicAdd(&s_cnt[c], 1);
    }
    __syncthreads();

    if (tid == 0) {
        int acc = 0;
        for (int c = 0; c < NC; c++) { s_start[c] = acc; acc += s_cnt[c]; }
        s_start[NC] = acc;
    }
    __syncthreads();

    // Stable counting-sort placement: one thread per class walks targets in
    // original order -> within-class original order preserved (argmax ties).
    if (tid < NC) {
        int pos = s_start[tid];
        for (int g = 0; g < GG; g++) {
            if ((int)s_lab[g * 5 + 4] == tid) {
                float x1 = s_lab[g * 5 + 0] * 512.0f;
                float y1 = s_lab[g * 5 + 1] * 512.0f;
                float x2 = s_lab[g * 5 + 2] * 512.0f;
                float y2 = s_lab[g * 5 + 3] * 512.0f;
                s_tbox[pos]  = make_float4(x1, y1, x2, y2);
                s_tarea[pos] = (x2 - x1) * (y2 - y1);
                pos++;
            }
        }
    }
    __syncthreads();

    const int winner_base = b * GG;
    const int pper = (PP + SPLIT - 1) / SPLIT;
    const int p0 = chunk * pper;
    const int p1 = (p0 + pper < PP) ? (p0 + pper) : PP;

    for (int p = p0 + tid; p < p1; p += THREADS) {
        const float* pr = preds + ((long)b * PP + p) * 6;
        float2 q0 = *(const float2*)(pr);       // x1, y1
        float2 q1 = *(const float2*)(pr + 2);   // x2, y2
        float2 q2 = *(const float2*)(pr + 4);   // score, cls

        float px1 = q0.x * 512.0f, py1 = q0.y * 512.0f;
        float px2 = q1.x * 512.0f, py2 = q1.y * 512.0f;
        float score = q2.x;
        float fcls  = q2.y;
        float parea = (px2 - px1) * (py2 - py1);
        int cls = (int)fcls;

        int   bi   = -1;
        float best = 0.5f;   // = IOU_THRESH: only > thresh targets can win

        if ((unsigned)cls < NC && score > 0.0f) {
            int t0 = s_start[cls], t1 = s_start[cls + 1];
            for (int t = t0; t < t1; t++) {
                float4 tb = s_tbox[t];
                float lx = fmaxf(px1, tb.x);
                float ly = fmaxf(py1, tb.y);
                float rx = fminf(px2, tb.z);
                float ry = fminf(py2, tb.w);
                float w = fmaxf(rx - lx, 0.0f);
                float h = fmaxf(ry - ly, 0.0f);
                float inter = w * h;
                if (inter > 0.0f) {
                    float denom = (parea + s_tarea[t]) - inter;  // ref op order
                    float iou = __fdiv_rn(inter, denom);          // IEEE div
                    if (iou > best) { best = iou; bi = t; }       // first-max
                }
            }
        }

        g_bi[b * PP + p] = (short)bi;
        if (bi >= 0) atomicMin(&g_winner[winner_base + bi], p);

        long o = ((long)b * PP + p) * 3;
        stats[o + 1] = score;
        stats[o + 2] = fcls;
    }
}

// ---------------------------------------------------------------------------
// Kernel 3: winner check -> correct flag
// ---------------------------------------------------------------------------
__global__ void mbe_fin_kernel(float* __restrict__ stats) {
    int i = blockIdx.x * blockDim.x + threadIdx.x;
    if (i < BB * PP) {
        int bi = g_bi[i];
        int b  = i / PP;
        int p  = i - b * PP;
        float c = 0.0f;
        if (bi >= 0 && g_winner[b * GG + bi] == p) c = 1.0f;
        stats[(long)i * 3] = c;
    }
}

// ---------------------------------------------------------------------------
extern "C" void kernel_launch(void* const* d_in, const int* in_sizes, int n_in,
                              void* d_out, int out_size) {
    const float* preds  = (const float*)d_in[0];   // (B,P,6)
    const float* labels = (const float*)d_in[1];   // (B,G,5)
    float* stats    = (float*)d_out;                       // (B,P,3)
    float* out_tcls = (float*)d_out + (long)BB * PP * 3;   // (B,G)

    (void)in_sizes; (void)n_in; (void)out_size;

    int initBlocks = (BB * GG + 255) / 256;
    mbe_init_kernel<<<initBlocks, 256>>>(labels, out_tcls);

    mbe_main_kernel<<<BB * SPLIT, THREADS>>>(preds, labels, stats);

    int finBlocks = (BB * PP + 255) / 256;
    mbe_fin_kernel<<<finBlocks, 256>>>(stats);
}

// round 12
// speedup vs baseline: 1.4687x; 1.4605x over previous
#include <cuda_runtime.h>
#include <climits>

// Problem constants
#define BB 64
#define PP 5000
#define GG 300
#define NC 20
#define THREADS 1024
#define PRED_PER_THREAD ((PP + THREADS - 1) / THREADS)   // 5

// ---------------------------------------------------------------------------
// Single fused kernel: one block per image.
//   Phase A: stage labels, emit tcls tail
//   Phase B: class histogram -> prefix -> warp-per-class ballot scatter (stable)
//   Phase C: per-pred best-target search (registers), shared atomicMin winners
//   Phase D: winner check -> correct flag
// ---------------------------------------------------------------------------
__global__ __launch_bounds__(THREADS)
void mbe_fused_kernel(const float* __restrict__ preds,
                      const float* __restrict__ labels,
                      float* __restrict__ stats,
                      float* __restrict__ out_tcls) {
    __shared__ float  s_lab[GG * 5];
    __shared__ float4 s_tbox[GG];      // scaled (x1,y1,x2,y2), class-sorted
    __shared__ float  s_tarea[GG];
    __shared__ int    s_start[NC + 1];
    __shared__ int    s_cnt[NC];
    __shared__ int    s_winner[GG];    // min pred index claiming each target

    const int b    = blockIdx.x;
    const int tid  = threadIdx.x;
    const int wid  = tid >> 5;
    const int lane = tid & 31;

    // ---- Phase A: stage labels, init counters/winners, emit tcls ----
    const float* lab = labels + (long)b * GG * 5;
    for (int i = tid; i < GG * 5; i += THREADS) s_lab[i] = lab[i];
    if (tid < NC) s_cnt[tid] = 0;
    if (tid < GG) s_winner[tid] = INT_MAX;
    __syncthreads();

    if (tid < GG) {
        float fc = s_lab[tid * 5 + 4];
        out_tcls[b * GG + tid] = fc;
        atomicAdd(&s_cnt[(int)fc], 1);
    }
    __syncthreads();

    if (tid == 0) {
        int acc = 0;
        #pragma unroll
        for (int c = 0; c < NC; c++) { s_start[c] = acc; acc += s_cnt[c]; }
        s_start[NC] = acc;
    }
    __syncthreads();

    // ---- Phase B: stable scatter, one warp per class via ballot prefix ----
    if (wid < NC) {
        const int c = wid;
        int base = s_start[c];
        #pragma unroll
        for (int g0 = 0; g0 < GG; g0 += 32) {
            int g = g0 + lane;
            bool m = (g < GG) && ((int)s_lab[g * 5 + 4] == c);
            unsigned msk = __ballot_sync(0xffffffffu, m);
            if (m) {
                int pos = base + __popc(msk & ((1u << lane) - 1u));
                float x1 = s_lab[g * 5 + 0] * 512.0f;
                float y1 = s_lab[g * 5 + 1] * 512.0f;
                float x2 = s_lab[g * 5 + 2] * 512.0f;
                float y2 = s_lab[g * 5 + 3] * 512.0f;
                s_tbox[pos]  = make_float4(x1, y1, x2, y2);
                s_tarea[pos] = (x2 - x1) * (y2 - y1);
            }
            base += __popc(msk);
        }
    }
    __syncthreads();

    // ---- Phase C: per-pred candidate search + shared winner claim ----
    const float* pbase = preds + (long)b * PP * 6;
    float* sbase = stats + (long)b * PP * 3;

    int my_bi[PRED_PER_THREAD];

    #pragma unroll
    for (int i = 0; i < PRED_PER_THREAD; i++) {
        my_bi[i] = -1;
        int p = tid + i * THREADS;
        if (p < PP) {
            const float* pr = pbase + p * 6;
            float2 q0 = *(const float2*)(pr);       // x1, y1
            float2 q1 = *(const float2*)(pr + 2);   // x2, y2
            float2 q2 = *(const float2*)(pr + 4);   // score, cls

            float px1 = q0.x * 512.0f, py1 = q0.y * 512.0f;
            float px2 = q1.x * 512.0f, py2 = q1.y * 512.0f;
            float score = q2.x;
            float fcls  = q2.y;
            float parea = (px2 - px1) * (py2 - py1);
            int cls = (int)fcls;

            int   bi   = -1;
            float best = 0.5f;   // = IOU_THRESH: only > thresh can win

            if ((unsigned)cls < NC && score > 0.0f) {
                int t1 = s_start[cls + 1];
                for (int t = s_start[cls]; t < t1; t++) {
                    float4 tb = s_tbox[t];
                    float lx = fmaxf(px1, tb.x);
                    float ly = fmaxf(py1, tb.y);
                    float rx = fminf(px2, tb.z);
                    float ry = fminf(py2, tb.w);
                    float w = fmaxf(rx - lx, 0.0f);
                    float h = fmaxf(ry - ly, 0.0f);
                    float inter = w * h;
                    if (inter > 0.0f) {
                        float denom = (parea + s_tarea[t]) - inter; // ref order
                        float iou = __fdiv_rn(inter, denom);        // IEEE div
                        if (iou > best) { best = iou; bi = t; }     // first-max
                    }
                }
            }

            my_bi[i] = bi;
            if (bi >= 0) atomicMin(&s_winner[bi], p);

            long o = (long)p * 3;
            sbase[o + 1] = score;
            sbase[o + 2] = fcls;
        }
    }
    __syncthreads();

    // ---- Phase D: winner check -> correct flag ----
    #pragma unroll
    for (int i = 0; i < PRED_PER_THREAD; i++) {
        int p = tid + i * THREADS;
        if (p < PP) {
            int bi = my_bi[i];
            float c = (bi >= 0 && s_winner[bi] == p) ? 1.0f : 0.0f;
            sbase[(long)p * 3] = c;
        }
    }
}

// ---------------------------------------------------------------------------
extern "C" void kernel_launch(void* const* d_in, const int* in_sizes, int n_in,
                              void* d_out, int out_size) {
    const float* preds  = (const float*)d_in[0];   // (B,P,6)
    const float* labels = (const float*)d_in[1];   // (B,G,5)
    float* stats    = (float*)d_out;                       // (B,P,3)
    float* out_tcls = (float*)d_out + (long)BB * PP * 3;   // (B,G)

    (void)in_sizes; (void)n_in; (void)out_size;

    mbe_fused_kernel<<<BB, THREADS>>>(preds, labels, stats, out_tcls);
}

// round 13
// speedup vs baseline: 1.8104x; 1.2326x over previous
#include <cuda_runtime.h>
#include <climits>

// Problem constants
#define BB 64
#define PP 5000
#define GG 300
#define NC 20
#define THREADS 1024
#define HALF (PP / 2)            // 2500 preds per block
#define NBLOCKS (BB * 2)         // 128 blocks: 2 per image, all wave-1 resident
#define ROUNDS 3                 // ceil(HALF / THREADS)

// Scratch (device globals -- no allocation allowed)
__device__ int      g_winner[BB * GG];   // min pred index claiming each target
__device__ unsigned g_count;             // barrier arrival counter (self-resetting)
__device__ unsigned g_sense;             // barrier sense flag  (returns to 0 per launch)

// Sense-reversing grid barrier. All NBLOCKS blocks are co-resident (128 blocks,
// 1024 thr, ~20KB smem => fits wave 1 on 148 SMs), so spinning is safe.
// State (g_count=0, g_sense=0) is restored by the end of each launch -> safe
// under CUDA-graph replay.
__device__ __forceinline__ void grid_barrier(unsigned sense_val) {
    __syncthreads();
    if (threadIdx.x == 0) {
        __threadfence();                       // publish prior global writes
        unsigned t = atomicAdd(&g_count, 1u);
        if (t == NBLOCKS - 1) {
            atomicExch(&g_count, 0u);          // reset for next barrier/launch
            __threadfence();
            atomicExch(&g_sense, sense_val);   // release
        } else {
            while (atomicAdd(&g_sense, 0u) != sense_val) __nanosleep(64);
        }
        __threadfence();                       // acquire others' global writes
    }
    __syncthreads();
}

// ---------------------------------------------------------------------------
// One kernel, 2 blocks per image. Per block:
//   reset half of image's winners; stage labels; stable class-sort targets;
//   unstable class-sort OWN 2500 preds (warp-uniform inner loops);
//   [grid barrier]  claims via global atomicMin  [grid barrier]  winner check.
// ---------------------------------------------------------------------------
__global__ __launch_bounds__(THREADS)
void mbe_fused_kernel(const float* __restrict__ preds,
                      const float* __restrict__ labels,
                      float* __restrict__ stats,
                      float* __restrict__ out_tcls) {
    __shared__ float          s_lab[GG * 5];
    __shared__ float4         s_tbox[GG];       // scaled boxes, class-sorted (stable)
    __shared__ float          s_tarea[GG];
    __shared__ int            s_tstart[NC + 1];
    __shared__ int            s_tcnt[NC];
    __shared__ int            s_pcnt[NC];
    __shared__ int            s_pofs[NC];       // scatter cursors for preds
    __shared__ unsigned short s_sorted[HALF];   // local pred idx, class-grouped
    __shared__ unsigned char  s_pcls[HALF];

    const int img  = blockIdx.x >> 1;
    const int half = blockIdx.x & 1;
    const int tid  = threadIdx.x;
    const int wid  = tid >> 5;
    const int lane = tid & 31;

    const float* lab    = labels + (long)img * GG * 5;
    const float* pbase  = preds + (long)img * PP * 6;
    float*       sbase  = stats + (long)img * PP * 3;
    const int    p_off  = half * HALF;

    // ---- Phase A: reset winners, stage labels + pred classes ----
    if (tid < GG / 2) g_winner[img * GG + half * (GG / 2) + tid] = INT_MAX;
    for (int i = tid; i < GG * 5; i += THREADS) s_lab[i] = lab[i];
    for (int j = tid; j < HALF; j += THREADS)
        s_pcls[j] = (unsigned char)(int)pbase[(p_off + j) * 6 + 5];
    if (tid < NC) { s_tcnt[tid] = 0; s_pcnt[tid] = 0; }
    __syncthreads();

    // ---- Phase B: histograms ----
    if (tid < GG) {
        float fc = s_lab[tid * 5 + 4];
        if (half == 0) out_tcls[img * GG + tid] = fc;
        atomicAdd(&s_tcnt[(int)fc], 1);
    }
    for (int j = tid; j < HALF; j += THREADS) atomicAdd(&s_pcnt[s_pcls[j]], 1);
    __syncthreads();

    if (tid == 0) {                 // target prefix
        int acc = 0;
        #pragma unroll
        for (int c = 0; c < NC; c++) { s_tstart[c] = acc; acc += s_tcnt[c]; }
        s_tstart[NC] = acc;
    }
    if (tid == 32) {                // pred prefix (parallel warp)
        int acc = 0;
        #pragma unroll
        for (int c = 0; c < NC; c++) { s_pofs[c] = acc; acc += s_pcnt[c]; }
    }
    __syncthreads();

    // Stable target scatter: one warp per class, ballot prefix (preserves
    // original within-class order -> argmax first-max ties identical to ref).
    if (wid < NC) {
        const int c = wid;
        int base = s_tstart[c];
        #pragma unroll
        for (int g0 = 0; g0 < GG; g0 += 32) {
            int g = g0 + lane;
            bool m = (g < GG) && ((int)s_lab[g * 5 + 4] == c);
            unsigned msk = __ballot_sync(0xffffffffu, m);
            if (m) {
                int pos = base + __popc(msk & ((1u << lane) - 1u));
                float x1 = s_lab[g * 5 + 0] * 512.0f;
                float y1 = s_lab[g * 5 + 1] * 512.0f;
                float x2 = s_lab[g * 5 + 2] * 512.0f;
                float y2 = s_lab[g * 5 + 3] * 512.0f;
                s_tbox[pos]  = make_float4(x1, y1, x2, y2);
                s_tarea[pos] = (x2 - x1) * (y2 - y1);
            }
            base += __popc(msk);
        }
    }
    // Unstable pred scatter (order within class irrelevant: atomicMin claims).
    for (int j = tid; j < HALF; j += THREADS) {
        int pos = atomicAdd(&s_pofs[s_pcls[j]], 1);
        s_sorted[pos] = (unsigned short)j;
    }
    __syncthreads();

    // ---- barrier A: all winner resets done before any claims ----
    grid_barrier(1u);

    // ---- Phase C: class-grouped per-pred search + global winner claim ----
    int my_bi[ROUNDS];
    int my_p[ROUNDS];

    #pragma unroll
    for (int k = 0; k < ROUNDS; k++) {
        my_bi[k] = -1; my_p[k] = -1;
        int j = tid + k * THREADS;
        if (j < HALF) {
            int p = p_off + (int)s_sorted[j];
            my_p[k] = p;
            const float* pr = pbase + p * 6;
            float2 q0 = *(const float2*)(pr);       // x1, y1
            float2 q1 = *(const float2*)(pr + 2);   // x2, y2
            float2 q2 = *(const float2*)(pr + 4);   // score, cls

            float px1 = q0.x * 512.0f, py1 = q0.y * 512.0f;
            float px2 = q1.x * 512.0f, py2 = q1.y * 512.0f;
            float score = q2.x;
            float fcls  = q2.y;
            float parea = (px2 - px1) * (py2 - py1);
            int cls = (int)fcls;

            int   bi   = -1;
            float best = 0.5f;   // = IOU_THRESH: only > thresh can win

            if ((unsigned)cls < NC && score > 0.0f) {
                int t1 = s_tstart[cls + 1];
                for (int t = s_tstart[cls]; t < t1; t++) {
                    float4 tb = s_tbox[t];
                    float lx = fmaxf(px1, tb.x);
                    float ly = fmaxf(py1, tb.y);
                    float rx = fminf(px2, tb.z);
                    float ry = fminf(py2, tb.w);
                    float w = fmaxf(rx - lx, 0.0f);
                    float h = fmaxf(ry - ly, 0.0f);
                    float inter = w * h;
                    if (inter > 0.0f) {
                        float denom = (parea + s_tarea[t]) - inter; // ref order
                        float iou = __fdiv_rn(inter, denom);        // IEEE div
                        if (iou > best) { best = iou; bi = t; }     // first-max
                    }
                }
            }

            my_bi[k] = bi;
            if (bi >= 0) atomicMin(&g_winner[img * GG + bi], p);

            long o = (long)p * 3;
            sbase[o + 1] = score;
            sbase[o + 2] = fcls;
        }
    }

    // ---- barrier B: all claims visible before winner check ----
    grid_barrier(0u);

    // ---- Phase D: winner check -> correct flag ----
    #pragma unroll
    for (int k = 0; k < ROUNDS; k++) {
        if (my_p[k] >= 0) {
            int bi = my_bi[k];
            float c = (bi >= 0 && g_winner[img * GG + bi] == my_p[k]) ? 1.0f : 0.0f;
            sbase[(long)my_p[k] * 3] = c;
        }
    }
}

// ---------------------------------------------------------------------------
extern "C" void kernel_launch(void* const* d_in, const int* in_sizes, int n_in,
                              void* d_out, int out_size) {
    const float* preds  = (const float*)d_in[0];   // (B,P,6)
    const float* labels = (const float*)d_in[1];   // (B,G,5)
    float* stats    = (float*)d_out;                       // (B,P,3)
    float* out_tcls = (float*)d_out + (long)BB * PP * 3;   // (B,G)

    (void)in_sizes; (void)n_in; (void)out_size;

    mbe_fused_kernel<<<NBLOCKS, THREADS>>>(preds, labels, stats, out_tcls);
}

// round 14
// speedup vs baseline: 1.9670x; 1.0865x over previous
#include <cuda_runtime.h>
#include <climits>

// Problem constants
#define BB 64
#define PP 5000
#define GG 300
#define NC 20
#define THREADS 1024
#define HALF (PP / 2)            // 2500 preds per block
#define NBLOCKS (BB * 2)         // 128 blocks: 2 per image, all wave-1 resident
#define ROUNDS 3                 // ceil(HALF / THREADS)

// Scratch (device globals -- no allocation allowed)
__device__ int      g_winner[BB * GG];   // min pred index claiming each target
__device__ unsigned g_barA[BB];          // pairwise barrier counters (self-reset to 0)
__device__ unsigned g_barB[BB];

// Pairwise (2-block) barrier: last arriver resets counter to 0, which is also
// the release. Counter ends at 0 every launch -> CUDA-graph-replay safe.
// The paired blocks do identical-size work, so the spin is typically 1 poll.
__device__ __forceinline__ void pair_barrier(unsigned* ctr) {
    __syncthreads();
    if (threadIdx.x == 0) {
        __threadfence();                       // publish prior global writes
        unsigned old = atomicAdd(ctr, 1u);
        if (old == 1u) {
            atomicExch(ctr, 0u);               // release + reset
        } else {
            while (atomicAdd(ctr, 0u) != 0u) __nanosleep(32);
        }
        __threadfence();                       // acquire partner's writes
    }
    __syncthreads();
}

// ---------------------------------------------------------------------------
// One kernel, 2 blocks per image.
// ---------------------------------------------------------------------------
__global__ __launch_bounds__(THREADS)
void mbe_fused_kernel(const float* __restrict__ preds,
                      const float* __restrict__ labels,
                      float* __restrict__ stats,
                      float* __restrict__ out_tcls) {
    __shared__ float          s_lab[GG * 5];
    __shared__ float4         s_tbox[GG];       // scaled boxes, class-sorted (stable)
    __shared__ float          s_tarea[GG];
    __shared__ int            s_tstart[NC + 1];
    __shared__ int            s_tcnt[NC];
    __shared__ int            s_pcnt[NC + 1];   // class 20 = dead (score<=0)
    __shared__ int            s_pofs[NC + 1];
    __shared__ unsigned short s_sorted[HALF];   // local pred idx, class-grouped
    __shared__ unsigned char  s_pcls[HALF];     // class of local pred (20 = dead)

    const int img  = blockIdx.x >> 1;
    const int half = blockIdx.x & 1;
    const int tid  = threadIdx.x;
    const int wid  = tid >> 5;
    const int lane = tid & 31;

    const float* lab    = labels + (long)img * GG * 5;
    const float* pbase  = preds + (long)img * PP * 6;
    float*       sbase  = stats + (long)img * PP * 3;
    const int    p_off  = half * HALF;
    int*         winner = g_winner + img * GG;

    // ---- Phase A: reset winners; stage labels; read (score,cls), emit stats
    //      tail columns immediately (ascending p -> near-coalesced) ----
    if (tid < GG / 2) winner[half * (GG / 2) + tid] = INT_MAX;
    for (int i = tid; i < GG * 5; i += THREADS) s_lab[i] = lab[i];
    if (tid <= NC) s_pcnt[tid] = 0;
    if (tid < NC)  s_tcnt[tid] = 0;
    __syncthreads();

    for (int j = tid; j < HALF; j += THREADS) {
        int p = p_off + j;
        float2 sc = *(const float2*)(pbase + p * 6 + 4);   // score, cls
        int c = (int)sc.y;
        if (!(sc.x > 0.0f) || (unsigned)c >= NC) c = NC;   // dead bucket
        s_pcls[j] = (unsigned char)c;
        atomicAdd(&s_pcnt[c], 1);
        long o = (long)p * 3;
        sbase[o + 1] = sc.x;
        sbase[o + 2] = sc.y;
    }

    // target histogram + tcls output
    if (tid < GG) {
        float fc = s_lab[tid * 5 + 4];
        if (half == 0) out_tcls[img * GG + tid] = fc;
        atomicAdd(&s_tcnt[(int)fc], 1);
    }
    __syncthreads();

    if (tid == 0) {                 // target prefix
        int acc = 0;
        #pragma unroll
        for (int c = 0; c < NC; c++) { s_tstart[c] = acc; acc += s_tcnt[c]; }
        s_tstart[NC] = acc;
    }
    if (tid == 32) {                // pred prefix (parallel warp)
        int acc = 0;
        #pragma unroll
        for (int c = 0; c <= NC; c++) { s_pofs[c] = acc; acc += s_pcnt[c]; }
    }
    __syncthreads();

    // Stable target scatter: one warp per class, ballot prefix (preserves
    // original within-class order -> argmax first-max ties identical to ref).
    if (wid < NC) {
        const int c = wid;
        int base = s_tstart[c];
        #pragma unroll
        for (int g0 = 0; g0 < GG; g0 += 32) {
            int g = g0 + lane;
            bool m = (g < GG) && ((int)s_lab[g * 5 + 4] == c);
            unsigned msk = __ballot_sync(0xffffffffu, m);
            if (m) {
                int pos = base + __popc(msk & ((1u << lane) - 1u));
                float x1 = s_lab[g * 5 + 0] * 512.0f;
                float y1 = s_lab[g * 5 + 1] * 512.0f;
                float x2 = s_lab[g * 5 + 2] * 512.0f;
                float y2 = s_lab[g * 5 + 3] * 512.0f;
                s_tbox[pos]  = make_float4(x1, y1, x2, y2);
                s_tarea[pos] = (x2 - x1) * (y2 - y1);
            }
            base += __popc(msk);
        }
    }
    // Unstable pred scatter (order within class irrelevant: atomicMin claims).
    for (int j = tid; j < HALF; j += THREADS) {
        int pos = atomicAdd(&s_pofs[s_pcls[j]], 1);
        s_sorted[pos] = (unsigned short)j;
    }
    __syncthreads();

    // ---- barrier A: partner's winner resets done before any claims ----
    pair_barrier(&g_barA[img]);

    // ---- Phase C: prefetch all rounds' pred boxes (deep MLP), then compute ----
    int   my_p[ROUNDS];
    int   my_cls[ROUNDS];
    float bx1[ROUNDS], by1[ROUNDS], bx2[ROUNDS], by2[ROUNDS];

    #pragma unroll
    for (int k = 0; k < ROUNDS; k++) {
        my_p[k] = -1; my_cls[k] = NC;
        int j = tid + k * THREADS;
        if (j < HALF) {
            int jj = (int)s_sorted[j];
            my_p[k]   = p_off + jj;
            my_cls[k] = s_pcls[jj];
            const float* pr = pbase + (long)my_p[k] * 6;
            float2 q0 = *(const float2*)(pr);       // x1, y1
            float2 q1 = *(const float2*)(pr + 2);   // x2, y2
            bx1[k] = q0.x * 512.0f; by1[k] = q0.y * 512.0f;
            bx2[k] = q1.x * 512.0f; by2[k] = q1.y * 512.0f;
        }
    }

    int my_bi[ROUNDS];
    #pragma unroll
    for (int k = 0; k < ROUNDS; k++) {
        int   bi   = -1;
        float best = 0.5f;   // = IOU_THRESH: only > thresh can win
        if (my_cls[k] < NC) {
            float px1 = bx1[k], py1 = by1[k], px2 = bx2[k], py2 = by2[k];
            float parea = (px2 - px1) * (py2 - py1);
            int t1 = s_tstart[my_cls[k] + 1];
            for (int t = s_tstart[my_cls[k]]; t < t1; t++) {
                float4 tb = s_tbox[t];
                float lx = fmaxf(px1, tb.x);
                float ly = fmaxf(py1, tb.y);
                float rx = fminf(px2, tb.z);
                float ry = fminf(py2, tb.w);
                float w = fmaxf(rx - lx, 0.0f);
                float h = fmaxf(ry - ly, 0.0f);
                float inter = w * h;
                if (inter > 0.0f) {
                    float denom = (parea + s_tarea[t]) - inter;  // ref op order
                    float iou = __fdiv_rn(inter, denom);         // IEEE div
                    if (iou > best) { best = iou; bi = t; }      // first-max
                }
            }
        }
        my_bi[k] = bi;
        if (bi >= 0) atomicMin(&winner[bi], my_p[k]);
    }

    // ---- barrier B: all claims visible before winner check ----
    pair_barrier(&g_barB[img]);

    // ---- Phase D: winner check -> correct flag ----
    #pragma unroll
    for (int k = 0; k < ROUNDS; k++) {
        if (my_p[k] >= 0) {
            int bi = my_bi[k];
            float c = (bi >= 0 && winner[bi] == my_p[k]) ? 1.0f : 0.0f;
            sbase[(long)my_p[k] * 3] = c;
        }
    }
}

// ---------------------------------------------------------------------------
extern "C" void kernel_launch(void* const* d_in, const int* in_sizes, int n_in,
                              void* d_out, int out_size) {
    const float* preds  = (const float*)d_in[0];   // (B,P,6)
    const float* labels = (const float*)d_in[1];   // (B,G,5)
    float* stats    = (float*)d_out;                       // (B,P,3)
    float* out_tcls = (float*)d_out + (long)BB * PP * 3;   // (B,G)

    (void)in_sizes; (void)n_in; (void)out_size;

    mbe_fused_kernel<<<NBLOCKS, THREADS>>>(preds, labels, stats, out_tcls);
}

// round 17
// speedup vs baseline: 2.0283x; 1.0312x over previous
#include <cuda_runtime.h>
#include <climits>

// Problem constants
#define BB 64
#define PP 5000
#define GG 300
#define NC 20
#define THREADS 1024
#define HALF (PP / 2)            // 2500 preds per block
#define NBLOCKS (BB * 2)         // 128 blocks: 2 per image, all wave-1 resident
#define ROUNDS 3                 // ceil(HALF / THREADS)

#define ALIGN16(x) (((x) + 15) & ~15)

// Dynamic smem layout (bytes); every chunk 16B-aligned.
#define OFF_PBOX   0                                      // float4[HALF]  40000
#define OFF_STATS  ALIGN16(OFF_PBOX + HALF * 16)          // float[HALF*3] 30000
#define OFF_PAREA  ALIGN16(OFF_STATS + HALF * 12)         // float[HALF]   10000
#define OFF_LAB    ALIGN16(OFF_PAREA + HALF * 4)          // float[GG*5]    6000
#define OFF_TBOX   ALIGN16(OFF_LAB + GG * 5 * 4)          // float4[GG]     4800
#define OFF_TAREA  ALIGN16(OFF_TBOX + GG * 16)            // float[GG]      1200
#define OFF_SORTED ALIGN16(OFF_TAREA + GG * 4)            // u16[HALF]      5000
#define OFF_PCLS   ALIGN16(OFF_SORTED + HALF * 2)         // u8[HALF]       2500
#define OFF_MISC   ALIGN16(OFF_PCLS + HALF)               // ints (see below)
// misc needs: tstart 21 + tcnt 20 + pcnt 21 + pofs 21 = 83 ints -> 96 for slack
#define MISC_INTS  96
#define SMEM_TOTAL (OFF_MISC + MISC_INTS * 4)

// Scratch (device globals -- no allocation allowed)
__device__ int      g_winner[BB * GG];   // min pred index claiming each target
__device__ unsigned g_barA[BB];          // pairwise barrier counters (self-reset)
__device__ unsigned g_barB[BB];

// Pairwise (2-block) barrier: last arriver resets counter to 0 (= release).
// Counter ends at 0 every launch -> CUDA-graph-replay safe.
__device__ __forceinline__ void pair_barrier(unsigned* ctr) {
    __syncthreads();
    if (threadIdx.x == 0) {
        __threadfence();
        unsigned old = atomicAdd(ctr, 1u);
        if (old == 1u) {
            atomicExch(ctr, 0u);
        } else {
            while (atomicAdd(ctr, 0u) != 0u) __nanosleep(32);
        }
        __threadfence();
    }
    __syncthreads();
}

// ---------------------------------------------------------------------------
__global__ __launch_bounds__(THREADS)
void mbe_fused_kernel(const float* __restrict__ preds,
                      const float* __restrict__ labels,
                      float* __restrict__ stats,
                      float* __restrict__ out_tcls) {
    extern __shared__ char smem[];
    float4*         s_pbox   = (float4*)(smem + OFF_PBOX);   // scaled pred boxes
    float*          s_stats  = (float*)(smem + OFF_STATS);   // [correct,score,cls]*HALF
    float*          s_parea  = (float*)(smem + OFF_PAREA);
    float*          s_lab    = (float*)(smem + OFF_LAB);
    float4*         s_tbox   = (float4*)(smem + OFF_TBOX);   // class-sorted (stable)
    float*          s_tarea  = (float*)(smem + OFF_TAREA);
    unsigned short* s_sorted = (unsigned short*)(smem + OFF_SORTED);
    unsigned char*  s_pcls   = (unsigned char*)(smem + OFF_PCLS);
    int*            s_tstart = (int*)(smem + OFF_MISC);            // 21 ints
    int*            s_tcnt   = s_tstart + (NC + 1);                // 20 ints
    int*            s_pcnt   = s_tcnt + NC;                        // 21 ints
    int*            s_pofs   = s_pcnt + (NC + 1);                  // 21 ints (=83 total < 96)

    const int img  = blockIdx.x >> 1;
    const int half = blockIdx.x & 1;
    const int tid  = threadIdx.x;
    const int wid  = tid >> 5;
    const int lane = tid & 31;

    const float* lab    = labels + (long)img * GG * 5;
    const float* pbase  = preds + ((long)img * PP + half * HALF) * 6;
    float*       sbase  = stats + ((long)img * PP + half * HALF) * 3;
    int*         winner = g_winner + img * GG;

    // ---- Phase A: reset winners; coalesced pred sweep -> smem SoA; labels ----
    if (tid < GG / 2) winner[half * (GG / 2) + tid] = INT_MAX;
    for (int i = tid; i < GG * 5; i += THREADS) s_lab[i] = lab[i];
    if (tid <= NC) { s_pcnt[tid] = 0; if (tid < NC) s_tcnt[tid] = 0; }
    __syncthreads();

    for (int j = tid; j < HALF; j += THREADS) {
        const float* pr = pbase + j * 6;
        float2 q0 = *(const float2*)(pr);       // x1, y1   (coalesced 24B/rec)
        float2 q1 = *(const float2*)(pr + 2);   // x2, y2
        float2 q2 = *(const float2*)(pr + 4);   // score, cls

        float px1 = q0.x * 512.0f, py1 = q0.y * 512.0f;
        float px2 = q1.x * 512.0f, py2 = q1.y * 512.0f;
        s_pbox[j]  = make_float4(px1, py1, px2, py2);
        s_parea[j] = (px2 - px1) * (py2 - py1);

        int c = (int)q2.y;
        if (!(q2.x > 0.0f) || (unsigned)c >= NC) c = NC;   // dead bucket
        s_pcls[j] = (unsigned char)c;
        atomicAdd(&s_pcnt[c], 1);

        s_stats[j * 3 + 0] = 0.0f;     // correct (default)
        s_stats[j * 3 + 1] = q2.x;     // score
        s_stats[j * 3 + 2] = q2.y;     // cls
    }

    if (tid < GG) {
        float fc = s_lab[tid * 5 + 4];
        if (half == 0) out_tcls[img * GG + tid] = fc;
        atomicAdd(&s_tcnt[(int)fc], 1);
    }
    __syncthreads();

    if (tid == 0) {                 // target prefix
        int acc = 0;
        #pragma unroll
        for (int c = 0; c < NC; c++) { s_tstart[c] = acc; acc += s_tcnt[c]; }
        s_tstart[NC] = acc;
    }
    if (tid == 32) {                // pred prefix (parallel warp)
        int acc = 0;
        #pragma unroll
        for (int c = 0; c <= NC; c++) { s_pofs[c] = acc; acc += s_pcnt[c]; }
    }
    __syncthreads();

    // Stable target scatter: one warp per class via ballot prefix (preserves
    // original within-class order -> argmax first-max ties identical to ref).
    if (wid < NC) {
        const int c = wid;
        int base = s_tstart[c];
        #pragma unroll
        for (int g0 = 0; g0 < GG; g0 += 32) {
            int g = g0 + lane;
            bool m = (g < GG) && ((int)s_lab[g * 5 + 4] == c);
            unsigned msk = __ballot_sync(0xffffffffu, m);
            if (m) {
                int pos = base + __popc(msk & ((1u << lane) - 1u));
                float x1 = s_lab[g * 5 + 0] * 512.0f;
                float y1 = s_lab[g * 5 + 1] * 512.0f;
                float x2 = s_lab[g * 5 + 2] * 512.0f;
                float y2 = s_lab[g * 5 + 3] * 512.0f;
                s_tbox[pos]  = make_float4(x1, y1, x2, y2);
                s_tarea[pos] = (x2 - x1) * (y2 - y1);
            }
            base += __popc(msk);
        }
    }
    // Unstable pred scatter (order within class irrelevant: atomicMin claims).
    for (int j = tid; j < HALF; j += THREADS) {
        int pos = atomicAdd(&s_pofs[s_pcls[j]], 1);
        s_sorted[pos] = (unsigned short)j;
    }
    __syncthreads();

    // ---- barrier A: partner's winner resets done before any claims ----
    pair_barrier(&g_barA[img]);

    // ---- Phase C: all-smem per-pred search (warp-uniform classes) ----
    int my_jj[ROUNDS];
    int my_bi[ROUNDS];

    #pragma unroll
    for (int k = 0; k < ROUNDS; k++) {
        my_jj[k] = -1;
        int bi = -1;
        int j = tid + k * THREADS;
        if (j < HALF) {
            int jj  = (int)s_sorted[j];
            int cls = s_pcls[jj];
            my_jj[k] = jj;
            if (cls < NC) {
                float4 pb   = s_pbox[jj];
                float parea = s_parea[jj];
                float best  = 0.5f;   // = IOU_THRESH: only > thresh can win
                int t1 = s_tstart[cls + 1];
                for (int t = s_tstart[cls]; t < t1; t++) {
                    float4 tb = s_tbox[t];
                    float lx = fmaxf(pb.x, tb.x);
                    float ly = fmaxf(pb.y, tb.y);
                    float rx = fminf(pb.z, tb.z);
                    float ry = fminf(pb.w, tb.w);
                    float w = fmaxf(rx - lx, 0.0f);
                    float h = fmaxf(ry - ly, 0.0f);
                    float inter = w * h;
                    if (inter > 0.0f) {
                        float denom = (parea + s_tarea[t]) - inter; // ref order
                        float iou = __fdiv_rn(inter, denom);        // IEEE div
                        if (iou > best) { best = iou; bi = t; }     // first-max
                    }
                }
                if (bi >= 0) atomicMin(&winner[bi], half * HALF + jj);
            }
        }
        my_bi[k] = bi;
    }

    // ---- barrier B: all claims visible before winner check ----
    pair_barrier(&g_barB[img]);

    // ---- Phase D: mark winners in smem, then coalesced float4 flush ----
    #pragma unroll
    for (int k = 0; k < ROUNDS; k++) {
        int bi = my_bi[k];
        if (bi >= 0 && winner[bi] == half * HALF + my_jj[k])
            s_stats[my_jj[k] * 3] = 1.0f;
    }
    __syncthreads();

    {   // HALF*3 = 7500 floats = 1875 float4 exactly; both bases 16B-aligned
        const float4* src = (const float4*)s_stats;
        float4*       dst = (float4*)sbase;
        for (int i = tid; i < (HALF * 3) / 4; i += THREADS) dst[i] = src[i];
    }
}

// ---------------------------------------------------------------------------
extern "C" void kernel_launch(void* const* d_in, const int* in_sizes, int n_in,
                              void* d_out, int out_size) {
    const float* preds  = (const float*)d_in[0];   // (B,P,6)
    const float* labels = (const float*)d_in[1];   // (B,G,5)
    float* stats    = (float*)d_out;                       // (B,P,3)
    float* out_tcls = (float*)d_out + (long)BB * PP * 3;   // (B,G)

    (void)in_sizes; (void)n_in; (void)out_size;

    cudaFuncSetAttribute(mbe_fused_kernel,
                         cudaFuncAttributeMaxDynamicSharedMemorySize, SMEM_TOTAL);
    mbe_fused_kernel<<<NBLOCKS, THREADS, SMEM_TOTAL>>>(preds, labels, stats, out_tcls);
}